// round 1
// baseline (speedup 1.0000x reference)
#include <cuda_runtime.h>

// Problem constants
#define Bq 2
#define Sq 2048
#define Hq 8
#define DEPTHq 64
#define DMq 512
#define NTOK (Bq * Sq)        // 4096
#define NROWS (2 * NTOK)      // 8192 (emb rows then pe rows)
#define CC 1536               // Wq|Wk|Wv output columns
#define BHq (Bq * Hq)         // 16

// ---------------- device scratch (static, allocation-free) ----------------
__device__ float g_C[NROWS * CC];            // fused projection output (~50 MB)
__device__ float g_Qh[BHq * Sq * 128];       // [bh][s][128] = [Qs*scale, Qc*scale]
__device__ float g_Kh[BHq * Sq * 128];       // [bh][s][128] = [Kc, Kr]
__device__ float g_Vh[BHq * Sq * DEPTHq];    // [bh][s][64]
__device__ float g_Z[NTOK * DMq];            // [b*s][512]
__device__ float g_attn_fallback[(size_t)BHq * Sq * Sq]; // used only if d_out lacks attn

// ============================================================
// Kernel 1: fused projection GEMM
//   C[8192 x 1536] = [emb; pe] @ [Wq | Wk | Wv] + [bq|bk|bv]
// 128x128 block tile, BK=16, 256 threads, 8x8 per thread.
// ============================================================
__global__ void proj_gemm(const float* __restrict__ emb, const float* __restrict__ pe,
                          const float* __restrict__ Wq, const float* __restrict__ bq,
                          const float* __restrict__ Wk, const float* __restrict__ bk,
                          const float* __restrict__ Wv, const float* __restrict__ bv) {
    __shared__ float As[16][132];
    __shared__ float Bs[16][132];
    const int m0 = blockIdx.y * 128;
    const int n0 = blockIdx.x * 128;
    const int tid = threadIdx.x;
    const int tx = tid & 15, ty = tid >> 4;

    float acc[8][8];
#pragma unroll
    for (int i = 0; i < 8; i++)
#pragma unroll
        for (int j = 0; j < 8; j++) acc[i][j] = 0.f;

    for (int k0 = 0; k0 < DMq; k0 += 16) {
#pragma unroll
        for (int i = 0; i < 8; i++) {
            int idx = tid + i * 256;
            int k = idx & 15, m = idx >> 4;
            int row = m0 + m;
            const float* src = (row < NTOK) ? (emb + (size_t)row * DMq)
                                            : (pe + (size_t)(row - NTOK) * DMq);
            As[k][m] = src[k0 + k];
        }
#pragma unroll
        for (int i = 0; i < 8; i++) {
            int idx = tid + i * 256;
            int n = idx & 127, k = idx >> 7;
            int col = n0 + n;
            const float* W = (col < 512) ? Wq : (col < 1024 ? Wk : Wv);
            Bs[k][n] = W[(size_t)(k0 + k) * DMq + (col & 511)];
        }
        __syncthreads();
#pragma unroll
        for (int k = 0; k < 16; k++) {
            float a[8], bb[8];
#pragma unroll
            for (int i = 0; i < 8; i++) a[i] = As[k][ty * 8 + i];
#pragma unroll
            for (int j = 0; j < 8; j++) bb[j] = Bs[k][tx * 8 + j];
#pragma unroll
            for (int i = 0; i < 8; i++)
#pragma unroll
                for (int j = 0; j < 8; j++) acc[i][j] += a[i] * bb[j];
        }
        __syncthreads();
    }

#pragma unroll
    for (int i = 0; i < 8; i++) {
        int row = m0 + ty * 8 + i;
#pragma unroll
        for (int j = 0; j < 8; j++) {
            int col = n0 + tx * 8 + j;
            const float* bias = (col < 512) ? bq : (col < 1024 ? bk : bv);
            g_C[(size_t)row * CC + col] = acc[i][j] + bias[col & 511];
        }
    }
}

// ============================================================
// Kernel 2: rearrange projections into head-major packed Q̂/K̂/V.
// Q̂ = [ (Qc+Qr)*0.125 , Qc*0.125 ]  (scale = 1/sqrt(64))
// K̂ = [ Kc , Kr ]
// ============================================================
__global__ void rearrange_kernel() {
    int idx = blockIdx.x * blockDim.x + threadIdx.x;
    if (idx >= NTOK * DMq) return;
    int n = idx / DMq;   // token index (b*S+s)
    int c = idx % DMq;
    int b = n / Sq, s = n % Sq;
    int h = c / DEPTHq, d = c % DEPTHq;

    float Qc = g_C[(size_t)n * CC + c];
    float Qr = g_C[(size_t)(NTOK + n) * CC + c];
    float Kc = g_C[(size_t)n * CC + 512 + c];
    float Kr = g_C[(size_t)(NTOK + n) * CC + 512 + c];
    float Vv = g_C[(size_t)n * CC + 1024 + c];

    size_t base = ((size_t)(b * Hq + h) * Sq + s) * 128;
    g_Qh[base + d]       = (Qc + Qr) * 0.125f;
    g_Qh[base + 64 + d]  = Qc * 0.125f;
    g_Kh[base + d]       = Kc;
    g_Kh[base + 64 + d]  = Kr;
    g_Vh[((size_t)(b * Hq + h) * Sq + s) * DEPTHq + d] = Vv;
}

// ============================================================
// Kernel 3: logits GEMM per (b,h):
//   L[q][t] = sum_{d<128} Q̂[q][d] * K̂[t][d]   (scale already folded in)
// 128x128 block tile, BK=16, 256 threads, 8x8 per thread.
// ============================================================
__global__ void logits_gemm(float* __restrict__ attn) {
    const int bh = blockIdx.z;
    const int q0 = blockIdx.y * 128;
    const int t0 = blockIdx.x * 128;
    const float* Q = g_Qh + (size_t)bh * Sq * 128;
    const float* K = g_Kh + (size_t)bh * Sq * 128;
    float* out = attn + (size_t)bh * Sq * Sq;

    __shared__ float Qs[16][132];
    __shared__ float Ks[16][132];
    const int tid = threadIdx.x;
    const int tx = tid & 15, ty = tid >> 4;

    float acc[8][8];
#pragma unroll
    for (int i = 0; i < 8; i++)
#pragma unroll
        for (int j = 0; j < 8; j++) acc[i][j] = 0.f;

    for (int k0 = 0; k0 < 128; k0 += 16) {
#pragma unroll
        for (int i = 0; i < 8; i++) {
            int idx = tid + i * 256;
            int k = idx & 15, m = idx >> 4;
            Qs[k][m] = Q[(size_t)(q0 + m) * 128 + k0 + k];
            Ks[k][m] = K[(size_t)(t0 + m) * 128 + k0 + k];
        }
        __syncthreads();
#pragma unroll
        for (int k = 0; k < 16; k++) {
            float a[8], bb[8];
#pragma unroll
            for (int i = 0; i < 8; i++) a[i] = Qs[k][ty * 8 + i];
#pragma unroll
            for (int j = 0; j < 8; j++) bb[j] = Ks[k][tx * 8 + j];
#pragma unroll
            for (int i = 0; i < 8; i++)
#pragma unroll
                for (int j = 0; j < 8; j++) acc[i][j] += a[i] * bb[j];
        }
        __syncthreads();
    }

#pragma unroll
    for (int i = 0; i < 8; i++) {
        size_t row = (size_t)(q0 + ty * 8 + i) * Sq;
#pragma unroll
        for (int j = 0; j < 8; j++) {
            out[row + t0 + tx * 8 + j] = acc[i][j];
        }
    }
}

// ============================================================
// Kernel 4: in-place row softmax. One block per row (2048 elems, 256 thr x 8).
// ============================================================
__global__ void softmax_kernel(float* __restrict__ attn) {
    size_t row = blockIdx.x;
    float* p = attn + row * Sq;
    const int tid = threadIdx.x;

    float v[8];
    float m = -1e30f;
#pragma unroll
    for (int i = 0; i < 8; i++) {
        v[i] = p[tid + i * 256];
        m = fmaxf(m, v[i]);
    }
    __shared__ float redmax[8];
    __shared__ float redsum[8];
#pragma unroll
    for (int o = 16; o > 0; o >>= 1) m = fmaxf(m, __shfl_xor_sync(0xffffffffu, m, o));
    if ((tid & 31) == 0) redmax[tid >> 5] = m;
    __syncthreads();
    float mm = redmax[0];
#pragma unroll
    for (int i = 1; i < 8; i++) mm = fmaxf(mm, redmax[i]);

    float ssum = 0.f;
#pragma unroll
    for (int i = 0; i < 8; i++) {
        v[i] = __expf(v[i] - mm);
        ssum += v[i];
    }
#pragma unroll
    for (int o = 16; o > 0; o >>= 1) ssum += __shfl_xor_sync(0xffffffffu, ssum, o);
    if ((tid & 31) == 0) redsum[tid >> 5] = ssum;
    __syncthreads();
    float tot = 0.f;
#pragma unroll
    for (int i = 0; i < 8; i++) tot += redsum[i];
    float inv = 1.f / tot;
#pragma unroll
    for (int i = 0; i < 8; i++) p[tid + i * 256] = v[i] * inv;
}

// ============================================================
// Kernel 5: z = attn @ V per (b,h): [2048x2048] @ [2048x64]
// Block: 128 q-rows x 64 d-cols, BK=16, 256 threads, 8x4 per thread.
// Writes z into [b, s, h*64+d] layout (ready for final GEMM).
// ============================================================
__global__ void zv_gemm(const float* __restrict__ attn) {
    const int bh = blockIdx.y;
    const int q0 = blockIdx.x * 128;
    const int b = bh / Hq, h = bh % Hq;
    const float* P = attn + (size_t)bh * Sq * Sq;
    const float* V = g_Vh + (size_t)bh * Sq * DEPTHq;

    __shared__ float Ps[16][132];
    __shared__ float Vs[16][68];
    const int tid = threadIdx.x;
    const int tx = tid & 15, ty = tid >> 4;

    float acc[8][4];
#pragma unroll
    for (int i = 0; i < 8; i++)
#pragma unroll
        for (int j = 0; j < 4; j++) acc[i][j] = 0.f;

    for (int k0 = 0; k0 < Sq; k0 += 16) {
#pragma unroll
        for (int i = 0; i < 8; i++) {
            int idx = tid + i * 256;
            int kk = idx & 15, m = idx >> 4;
            Ps[kk][m] = P[(size_t)(q0 + m) * Sq + k0 + kk];
        }
#pragma unroll
        for (int i = 0; i < 4; i++) {
            int idx = tid + i * 256;
            int d = idx & 63, kk = idx >> 6;
            Vs[kk][d] = V[(size_t)(k0 + kk) * DEPTHq + d];
        }
        __syncthreads();
#pragma unroll
        for (int kk = 0; kk < 16; kk++) {
            float a[8], bb[4];
#pragma unroll
            for (int i = 0; i < 8; i++) a[i] = Ps[kk][ty * 8 + i];
#pragma unroll
            for (int j = 0; j < 4; j++) bb[j] = Vs[kk][tx * 4 + j];
#pragma unroll
            for (int i = 0; i < 8; i++)
#pragma unroll
                for (int j = 0; j < 4; j++) acc[i][j] += a[i] * bb[j];
        }
        __syncthreads();
    }

#pragma unroll
    for (int i = 0; i < 8; i++) {
        size_t srow = ((size_t)b * Sq + (q0 + ty * 8 + i)) * DMq + h * DEPTHq;
#pragma unroll
        for (int j = 0; j < 4; j++) g_Z[srow + tx * 4 + j] = acc[i][j];
    }
}

// ============================================================
// Kernel 6: out = z @ Wo + bo : [4096x512] @ [512x512]
// ============================================================
__global__ void out_gemm(const float* __restrict__ Wo, const float* __restrict__ bo,
                         float* __restrict__ out) {
    __shared__ float As[16][132];
    __shared__ float Bs[16][132];
    const int m0 = blockIdx.y * 128;
    const int n0 = blockIdx.x * 128;
    const int tid = threadIdx.x;
    const int tx = tid & 15, ty = tid >> 4;

    float acc[8][8];
#pragma unroll
    for (int i = 0; i < 8; i++)
#pragma unroll
        for (int j = 0; j < 8; j++) acc[i][j] = 0.f;

    for (int k0 = 0; k0 < DMq; k0 += 16) {
#pragma unroll
        for (int i = 0; i < 8; i++) {
            int idx = tid + i * 256;
            int k = idx & 15, m = idx >> 4;
            As[k][m] = g_Z[(size_t)(m0 + m) * DMq + k0 + k];
        }
#pragma unroll
        for (int i = 0; i < 8; i++) {
            int idx = tid + i * 256;
            int n = idx & 127, k = idx >> 7;
            Bs[k][n] = Wo[(size_t)(k0 + k) * DMq + n0 + n];
        }
        __syncthreads();
#pragma unroll
        for (int k = 0; k < 16; k++) {
            float a[8], bb[8];
#pragma unroll
            for (int i = 0; i < 8; i++) a[i] = As[k][ty * 8 + i];
#pragma unroll
            for (int j = 0; j < 8; j++) bb[j] = Bs[k][tx * 8 + j];
#pragma unroll
            for (int i = 0; i < 8; i++)
#pragma unroll
                for (int j = 0; j < 8; j++) acc[i][j] += a[i] * bb[j];
        }
        __syncthreads();
    }

#pragma unroll
    for (int i = 0; i < 8; i++) {
        size_t row = (size_t)(m0 + ty * 8 + i) * DMq;
#pragma unroll
        for (int j = 0; j < 8; j++) {
            int col = n0 + tx * 8 + j;
            out[row + col] = acc[i][j] + bo[col];
        }
    }
}

// ============================================================
// Launch
// ============================================================
extern "C" void kernel_launch(void* const* d_in, const int* in_sizes, int n_in,
                              void* d_out, int out_size) {
    const float* emb = (const float*)d_in[0];
    const float* pe  = (const float*)d_in[1];
    const float* Wq  = (const float*)d_in[2];
    const float* bq  = (const float*)d_in[3];
    const float* Wk  = (const float*)d_in[4];
    const float* bk  = (const float*)d_in[5];
    const float* Wv  = (const float*)d_in[6];
    const float* bv  = (const float*)d_in[7];
    const float* Wo  = (const float*)d_in[8];
    const float* bo  = (const float*)d_in[9];

    float* out = (float*)d_out;

    // Output layout: [out (B*S*DM) | attn (B*H*S*S)] if out_size covers both;
    // otherwise attn goes to device scratch.
    const long long need = (long long)NTOK * DMq + (long long)BHq * Sq * Sq;
    float* attn;
    if ((long long)out_size >= need) {
        attn = out + (size_t)NTOK * DMq;
    } else {
        float* p = nullptr;
        cudaGetSymbolAddress((void**)&p, g_attn_fallback);
        attn = p;
    }

    // 1. fused projections
    {
        dim3 grid(CC / 128, NROWS / 128);
        proj_gemm<<<grid, 256>>>(emb, pe, Wq, bq, Wk, bk, Wv, bv);
    }
    // 2. rearrange
    {
        int total = NTOK * DMq;
        rearrange_kernel<<<(total + 255) / 256, 256>>>();
    }
    // 3. logits
    {
        dim3 grid(Sq / 128, Sq / 128, BHq);
        logits_gemm<<<grid, 256>>>(attn);
    }
    // 4. softmax (in place)
    {
        softmax_kernel<<<BHq * Sq, 256>>>(attn);
    }
    // 5. z = attn @ V
    {
        dim3 grid(Sq / 128, BHq);
        zv_gemm<<<grid, 256>>>(attn);
    }
    // 6. out = z @ Wo + bo
    {
        dim3 grid(DMq / 128, NTOK / 128);
        out_gemm<<<grid, 256>>>(Wo, bo, out);
    }
}

// round 2
// speedup vs baseline: 2.1346x; 2.1346x over previous
#include <cuda_runtime.h>
#include <cstdint>

// Problem constants
#define Bq 2
#define Sq 2048
#define Hq 8
#define DEPTHq 64
#define DMq 512
#define NTOK (Bq * Sq)        // 4096
#define NROWS (2 * NTOK)      // 8192 (emb rows then pe rows)
#define CC 1536               // Wq|Wk|Wv output columns
#define BHq (Bq * Hq)         // 16

// ---------------- device scratch (static, allocation-free) ----------------
__device__ float g_C[NROWS * CC];            // fused projection output
__device__ float g_Qh[BHq * Sq * 128];       // [bh][s][128] = [(Qc+Qr)*scale, Qc*scale]
__device__ float g_Kh[BHq * Sq * 128];       // [bh][s][128] = [Kc, Kr]
__device__ float g_Vh[BHq * Sq * DEPTHq];    // [bh][s][64]
__device__ float g_Z[NTOK * DMq];            // [b*s][512]
__device__ float g_attn_fallback[(size_t)BHq * Sq * Sq];

// ---------------- tf32 mma helpers ----------------
__device__ __forceinline__ uint32_t f2tf32(float f) {
    uint32_t u;
    asm("cvt.rna.tf32.f32 %0, %1;" : "=r"(u) : "f"(f));
    return u;
}

__device__ __forceinline__ void mma8(float* c, const uint32_t* a, const uint32_t* b) {
    asm volatile(
        "mma.sync.aligned.m16n8k8.row.col.f32.tf32.tf32.f32 "
        "{%0,%1,%2,%3}, {%4,%5,%6,%7}, {%8,%9}, {%0,%1,%2,%3};"
        : "+f"(c[0]), "+f"(c[1]), "+f"(c[2]), "+f"(c[3])
        : "r"(a[0]), "r"(a[1]), "r"(a[2]), "r"(a[3]),
          "r"(b[0]), "r"(b[1]));
}

// ============================================================
// Kernel 1: fused projection GEMM (tf32 tensor core)
//   C[8192 x 1536] = [emb; pe] @ [Wq | Wk | Wv] + [bq|bk|bv]
// 128x128 tile, BK=32, 256 threads = 8 warps (2x4), warp tile 64x32.
// ============================================================
__global__ void __launch_bounds__(256)
proj_gemm_tc(const float* __restrict__ emb, const float* __restrict__ pe,
             const float* __restrict__ Wq, const float* __restrict__ bq,
             const float* __restrict__ Wk, const float* __restrict__ bk,
             const float* __restrict__ Wv, const float* __restrict__ bv) {
    __shared__ uint32_t As[32][133];
    __shared__ uint32_t Bs[32][133];
    const int m0 = blockIdx.y * 128;
    const int n0 = blockIdx.x * 128;
    const int tid = threadIdx.x;
    const int wid = tid >> 5, lane = tid & 31;
    const int wm = (wid >> 2) * 64, wn = (wid & 3) * 32;
    const int lg = lane >> 2, lt = lane & 3;

    float acc[4][4][4];
#pragma unroll
    for (int i = 0; i < 4; i++)
#pragma unroll
        for (int j = 0; j < 4; j++)
#pragma unroll
            for (int r = 0; r < 4; r++) acc[i][j][r] = 0.f;

    for (int k0 = 0; k0 < DMq; k0 += 32) {
        // A: 128 rows x 32 k (transpose into k-major)
#pragma unroll
        for (int i = 0; i < 16; i++) {
            int idx = tid + i * 256;
            int k = idx & 31, m = idx >> 5;
            int row = m0 + m;
            const float* src = (row < NTOK) ? (emb + (size_t)row * DMq)
                                            : (pe + (size_t)(row - NTOK) * DMq);
            As[k][m] = f2tf32(src[k0 + k]);
        }
        // B: 32 k rows x 128 n cols (direct)
#pragma unroll
        for (int i = 0; i < 16; i++) {
            int idx = tid + i * 256;
            int n = idx & 127, k = idx >> 7;
            int col = n0 + n;
            const float* W = (col < 512) ? Wq : (col < 1024 ? Wk : Wv);
            Bs[k][n] = f2tf32(W[(size_t)(k0 + k) * DMq + (col & 511)]);
        }
        __syncthreads();
#pragma unroll
        for (int kc = 0; kc < 4; kc++) {
            int kb = kc * 8;
            uint32_t af[4][4], bf[4][2];
#pragma unroll
            for (int mi = 0; mi < 4; mi++) {
                int m = wm + mi * 16 + lg;
                af[mi][0] = As[kb + lt][m];
                af[mi][1] = As[kb + lt][m + 8];
                af[mi][2] = As[kb + 4 + lt][m];
                af[mi][3] = As[kb + 4 + lt][m + 8];
            }
#pragma unroll
            for (int ni = 0; ni < 4; ni++) {
                int n = wn + ni * 8 + lg;
                bf[ni][0] = Bs[kb + lt][n];
                bf[ni][1] = Bs[kb + 4 + lt][n];
            }
#pragma unroll
            for (int mi = 0; mi < 4; mi++)
#pragma unroll
                for (int ni = 0; ni < 4; ni++) mma8(acc[mi][ni], af[mi], bf[ni]);
        }
        __syncthreads();
    }

#pragma unroll
    for (int mi = 0; mi < 4; mi++) {
        int r0 = m0 + wm + mi * 16 + lg;
#pragma unroll
        for (int ni = 0; ni < 4; ni++) {
            int c0 = n0 + wn + ni * 8 + 2 * lt;
            const float* bias = (c0 < 512) ? bq : (c0 < 1024 ? bk : bv);
            float b0v = bias[c0 & 511], b1v = bias[(c0 + 1) & 511];
            float2 v0 = make_float2(acc[mi][ni][0] + b0v, acc[mi][ni][1] + b1v);
            float2 v1 = make_float2(acc[mi][ni][2] + b0v, acc[mi][ni][3] + b1v);
            *reinterpret_cast<float2*>(&g_C[(size_t)r0 * CC + c0]) = v0;
            *reinterpret_cast<float2*>(&g_C[(size_t)(r0 + 8) * CC + c0]) = v1;
        }
    }
}

// ============================================================
// Kernel 2: rearrange projections into head-major packed Q̂/K̂/V.
// ============================================================
__global__ void rearrange_kernel() {
    int idx = blockIdx.x * blockDim.x + threadIdx.x;
    if (idx >= NTOK * DMq) return;
    int n = idx / DMq;
    int c = idx % DMq;
    int b = n / Sq, s = n % Sq;
    int h = c / DEPTHq, d = c % DEPTHq;

    float Qc = g_C[(size_t)n * CC + c];
    float Qr = g_C[(size_t)(NTOK + n) * CC + c];
    float Kc = g_C[(size_t)n * CC + 512 + c];
    float Kr = g_C[(size_t)(NTOK + n) * CC + 512 + c];
    float Vv = g_C[(size_t)n * CC + 1024 + c];

    size_t base = ((size_t)(b * Hq + h) * Sq + s) * 128;
    g_Qh[base + d]      = (Qc + Qr) * 0.125f;
    g_Qh[base + 64 + d] = Qc * 0.125f;
    g_Kh[base + d]      = Kc;
    g_Kh[base + 64 + d] = Kr;
    g_Vh[((size_t)(b * Hq + h) * Sq + s) * DEPTHq + d] = Vv;
}

// ============================================================
// Kernel 3: logits GEMM per (b,h) (tf32 tensor core)
//   L[q][t] = sum_{d<128} Q̂[q][d] * K̂[t][d]
// ============================================================
__global__ void __launch_bounds__(256)
logits_gemm_tc(float* __restrict__ attn) {
    const int bh = blockIdx.z;
    const int q0 = blockIdx.y * 128;
    const int t0 = blockIdx.x * 128;
    const float* Q = g_Qh + (size_t)bh * Sq * 128;
    const float* K = g_Kh + (size_t)bh * Sq * 128;
    float* out = attn + (size_t)bh * Sq * Sq;

    __shared__ uint32_t As[32][133];
    __shared__ uint32_t Bs[32][133];
    const int tid = threadIdx.x;
    const int wid = tid >> 5, lane = tid & 31;
    const int wm = (wid >> 2) * 64, wn = (wid & 3) * 32;
    const int lg = lane >> 2, lt = lane & 3;

    float acc[4][4][4];
#pragma unroll
    for (int i = 0; i < 4; i++)
#pragma unroll
        for (int j = 0; j < 4; j++)
#pragma unroll
            for (int r = 0; r < 4; r++) acc[i][j][r] = 0.f;

    for (int k0 = 0; k0 < 128; k0 += 32) {
#pragma unroll
        for (int i = 0; i < 16; i++) {
            int idx = tid + i * 256;
            int k = idx & 31, m = idx >> 5;
            As[k][m] = f2tf32(Q[(size_t)(q0 + m) * 128 + k0 + k]);
            Bs[k][m] = f2tf32(K[(size_t)(t0 + m) * 128 + k0 + k]);
        }
        __syncthreads();
#pragma unroll
        for (int kc = 0; kc < 4; kc++) {
            int kb = kc * 8;
            uint32_t af[4][4], bf[4][2];
#pragma unroll
            for (int mi = 0; mi < 4; mi++) {
                int m = wm + mi * 16 + lg;
                af[mi][0] = As[kb + lt][m];
                af[mi][1] = As[kb + lt][m + 8];
                af[mi][2] = As[kb + 4 + lt][m];
                af[mi][3] = As[kb + 4 + lt][m + 8];
            }
#pragma unroll
            for (int ni = 0; ni < 4; ni++) {
                int n = wn + ni * 8 + lg;
                bf[ni][0] = Bs[kb + lt][n];
                bf[ni][1] = Bs[kb + 4 + lt][n];
            }
#pragma unroll
            for (int mi = 0; mi < 4; mi++)
#pragma unroll
                for (int ni = 0; ni < 4; ni++) mma8(acc[mi][ni], af[mi], bf[ni]);
        }
        __syncthreads();
    }

#pragma unroll
    for (int mi = 0; mi < 4; mi++) {
        int r0 = q0 + wm + mi * 16 + lg;
#pragma unroll
        for (int ni = 0; ni < 4; ni++) {
            int c0 = t0 + wn + ni * 8 + 2 * lt;
            *reinterpret_cast<float2*>(&out[(size_t)r0 * Sq + c0]) =
                make_float2(acc[mi][ni][0], acc[mi][ni][1]);
            *reinterpret_cast<float2*>(&out[(size_t)(r0 + 8) * Sq + c0]) =
                make_float2(acc[mi][ni][2], acc[mi][ni][3]);
        }
    }
}

// ============================================================
// Kernel 4: in-place row softmax (unchanged; ~81% DRAM SOL).
// ============================================================
__global__ void softmax_kernel(float* __restrict__ attn) {
    size_t row = blockIdx.x;
    float* p = attn + row * Sq;
    const int tid = threadIdx.x;

    float v[8];
    float m = -1e30f;
#pragma unroll
    for (int i = 0; i < 8; i++) {
        v[i] = p[tid + i * 256];
        m = fmaxf(m, v[i]);
    }
    __shared__ float redmax[8];
    __shared__ float redsum[8];
#pragma unroll
    for (int o = 16; o > 0; o >>= 1) m = fmaxf(m, __shfl_xor_sync(0xffffffffu, m, o));
    if ((tid & 31) == 0) redmax[tid >> 5] = m;
    __syncthreads();
    float mm = redmax[0];
#pragma unroll
    for (int i = 1; i < 8; i++) mm = fmaxf(mm, redmax[i]);

    float ssum = 0.f;
#pragma unroll
    for (int i = 0; i < 8; i++) {
        v[i] = __expf(v[i] - mm);
        ssum += v[i];
    }
#pragma unroll
    for (int o = 16; o > 0; o >>= 1) ssum += __shfl_xor_sync(0xffffffffu, ssum, o);
    if ((tid & 31) == 0) redsum[tid >> 5] = ssum;
    __syncthreads();
    float tot = 0.f;
#pragma unroll
    for (int i = 0; i < 8; i++) tot += redsum[i];
    float inv = 1.f / tot;
#pragma unroll
    for (int i = 0; i < 8; i++) p[tid + i * 256] = v[i] * inv;
}

// ============================================================
// Kernel 5: z = attn @ V per (b,h) (tf32 tensor core)
// Block tile 128(q) x 64(d), BK=32, 128 threads = 4 warps (2x2),
// warp tile 64x32.
// ============================================================
__global__ void __launch_bounds__(128)
zv_gemm_tc(const float* __restrict__ attn) {
    const int bh = blockIdx.y;
    const int q0 = blockIdx.x * 128;
    const int b = bh / Hq, h = bh % Hq;
    const float* P = attn + (size_t)bh * Sq * Sq;
    const float* V = g_Vh + (size_t)bh * Sq * DEPTHq;

    __shared__ uint32_t As[32][133];
    __shared__ uint32_t Bs[32][69];
    const int tid = threadIdx.x;
    const int wid = tid >> 5, lane = tid & 31;
    const int wm = (wid >> 1) * 64, wn = (wid & 1) * 32;
    const int lg = lane >> 2, lt = lane & 3;

    float acc[4][4][4];
#pragma unroll
    for (int i = 0; i < 4; i++)
#pragma unroll
        for (int j = 0; j < 4; j++)
#pragma unroll
            for (int r = 0; r < 4; r++) acc[i][j][r] = 0.f;

    for (int k0 = 0; k0 < Sq; k0 += 32) {
        // A: P tile 128 rows x 32 k -> k-major
#pragma unroll
        for (int i = 0; i < 32; i++) {
            int idx = tid + i * 128;
            int k = idx & 31, m = idx >> 5;
            As[k][m] = f2tf32(P[(size_t)(q0 + m) * Sq + k0 + k]);
        }
        // B: V tile 32 k rows x 64 d cols (direct)
#pragma unroll
        for (int i = 0; i < 16; i++) {
            int idx = tid + i * 128;
            int n = idx & 63, k = idx >> 6;
            Bs[k][n] = f2tf32(V[(size_t)(k0 + k) * DEPTHq + n]);
        }
        __syncthreads();
#pragma unroll
        for (int kc = 0; kc < 4; kc++) {
            int kb = kc * 8;
            uint32_t af[4][4], bf[4][2];
#pragma unroll
            for (int mi = 0; mi < 4; mi++) {
                int m = wm + mi * 16 + lg;
                af[mi][0] = As[kb + lt][m];
                af[mi][1] = As[kb + lt][m + 8];
                af[mi][2] = As[kb + 4 + lt][m];
                af[mi][3] = As[kb + 4 + lt][m + 8];
            }
#pragma unroll
            for (int ni = 0; ni < 4; ni++) {
                int n = wn + ni * 8 + lg;
                bf[ni][0] = Bs[kb + lt][n];
                bf[ni][1] = Bs[kb + 4 + lt][n];
            }
#pragma unroll
            for (int mi = 0; mi < 4; mi++)
#pragma unroll
                for (int ni = 0; ni < 4; ni++) mma8(acc[mi][ni], af[mi], bf[ni]);
        }
        __syncthreads();
    }

#pragma unroll
    for (int mi = 0; mi < 4; mi++) {
        int r0 = q0 + wm + mi * 16 + lg;
#pragma unroll
        for (int ni = 0; ni < 4; ni++) {
            int c0 = wn + ni * 8 + 2 * lt;
            size_t base0 = ((size_t)b * Sq + r0) * DMq + h * DEPTHq + c0;
            size_t base1 = ((size_t)b * Sq + r0 + 8) * DMq + h * DEPTHq + c0;
            *reinterpret_cast<float2*>(&g_Z[base0]) =
                make_float2(acc[mi][ni][0], acc[mi][ni][1]);
            *reinterpret_cast<float2*>(&g_Z[base1]) =
                make_float2(acc[mi][ni][2], acc[mi][ni][3]);
        }
    }
}

// ============================================================
// Kernel 6: out = z @ Wo + bo (tf32 tensor core): [4096x512]@[512x512]
// ============================================================
__global__ void __launch_bounds__(256)
out_gemm_tc(const float* __restrict__ Wo, const float* __restrict__ bo,
            float* __restrict__ out) {
    __shared__ uint32_t As[32][133];
    __shared__ uint32_t Bs[32][133];
    const int m0 = blockIdx.y * 128;
    const int n0 = blockIdx.x * 128;
    const int tid = threadIdx.x;
    const int wid = tid >> 5, lane = tid & 31;
    const int wm = (wid >> 2) * 64, wn = (wid & 3) * 32;
    const int lg = lane >> 2, lt = lane & 3;

    float acc[4][4][4];
#pragma unroll
    for (int i = 0; i < 4; i++)
#pragma unroll
        for (int j = 0; j < 4; j++)
#pragma unroll
            for (int r = 0; r < 4; r++) acc[i][j][r] = 0.f;

    for (int k0 = 0; k0 < DMq; k0 += 32) {
#pragma unroll
        for (int i = 0; i < 16; i++) {
            int idx = tid + i * 256;
            int k = idx & 31, m = idx >> 5;
            As[k][m] = f2tf32(g_Z[(size_t)(m0 + m) * DMq + k0 + k]);
        }
#pragma unroll
        for (int i = 0; i < 16; i++) {
            int idx = tid + i * 256;
            int n = idx & 127, k = idx >> 7;
            Bs[k][n] = f2tf32(Wo[(size_t)(k0 + k) * DMq + n0 + n]);
        }
        __syncthreads();
#pragma unroll
        for (int kc = 0; kc < 4; kc++) {
            int kb = kc * 8;
            uint32_t af[4][4], bf[4][2];
#pragma unroll
            for (int mi = 0; mi < 4; mi++) {
                int m = wm + mi * 16 + lg;
                af[mi][0] = As[kb + lt][m];
                af[mi][1] = As[kb + lt][m + 8];
                af[mi][2] = As[kb + 4 + lt][m];
                af[mi][3] = As[kb + 4 + lt][m + 8];
            }
#pragma unroll
            for (int ni = 0; ni < 4; ni++) {
                int n = wn + ni * 8 + lg;
                bf[ni][0] = Bs[kb + lt][n];
                bf[ni][1] = Bs[kb + 4 + lt][n];
            }
#pragma unroll
            for (int mi = 0; mi < 4; mi++)
#pragma unroll
                for (int ni = 0; ni < 4; ni++) mma8(acc[mi][ni], af[mi], bf[ni]);
        }
        __syncthreads();
    }

#pragma unroll
    for (int mi = 0; mi < 4; mi++) {
        int r0 = m0 + wm + mi * 16 + lg;
#pragma unroll
        for (int ni = 0; ni < 4; ni++) {
            int c0 = n0 + wn + ni * 8 + 2 * lt;
            float b0v = bo[c0], b1v = bo[c0 + 1];
            *reinterpret_cast<float2*>(&out[(size_t)r0 * DMq + c0]) =
                make_float2(acc[mi][ni][0] + b0v, acc[mi][ni][1] + b1v);
            *reinterpret_cast<float2*>(&out[(size_t)(r0 + 8) * DMq + c0]) =
                make_float2(acc[mi][ni][2] + b0v, acc[mi][ni][3] + b1v);
        }
    }
}

// ============================================================
// Launch
// ============================================================
extern "C" void kernel_launch(void* const* d_in, const int* in_sizes, int n_in,
                              void* d_out, int out_size) {
    const float* emb = (const float*)d_in[0];
    const float* pe  = (const float*)d_in[1];
    const float* Wq  = (const float*)d_in[2];
    const float* bq  = (const float*)d_in[3];
    const float* Wk  = (const float*)d_in[4];
    const float* bk  = (const float*)d_in[5];
    const float* Wv  = (const float*)d_in[6];
    const float* bv  = (const float*)d_in[7];
    const float* Wo  = (const float*)d_in[8];
    const float* bo  = (const float*)d_in[9];

    float* out = (float*)d_out;

    const long long need = (long long)NTOK * DMq + (long long)BHq * Sq * Sq;
    float* attn;
    if ((long long)out_size >= need) {
        attn = out + (size_t)NTOK * DMq;
    } else {
        float* p = nullptr;
        cudaGetSymbolAddress((void**)&p, g_attn_fallback);
        attn = p;
    }

    {
        dim3 grid(CC / 128, NROWS / 128);
        proj_gemm_tc<<<grid, 256>>>(emb, pe, Wq, bq, Wk, bk, Wv, bv);
    }
    {
        int total = NTOK * DMq;
        rearrange_kernel<<<(total + 255) / 256, 256>>>();
    }
    {
        dim3 grid(Sq / 128, Sq / 128, BHq);
        logits_gemm_tc<<<grid, 256>>>(attn);
    }
    {
        softmax_kernel<<<BHq * Sq, 256>>>(attn);
    }
    {
        dim3 grid(Sq / 128, BHq);
        zv_gemm_tc<<<grid, 128>>>(attn);
    }
    {
        dim3 grid(DMq / 128, NTOK / 128);
        out_gemm_tc<<<grid, 256>>>(Wo, bo, out);
    }
}

// round 3
// speedup vs baseline: 2.3101x; 1.0822x over previous
#include <cuda_runtime.h>
#include <cstdint>

// Problem constants
#define Bq 2
#define Sq 2048
#define Hq 8
#define DEPTHq 64
#define DMq 512
#define NTOK (Bq * Sq)        // 4096
#define NROWS (2 * NTOK)      // 8192
#define CC 1536               // Wq|Wk|Wv output columns
#define BHq (Bq * Hq)         // 16

// ---------------- device scratch ----------------
__device__ float g_C[NROWS * CC];
__device__ float g_Qh[BHq * Sq * 128];
__device__ float g_Kh[BHq * Sq * 128];
__device__ float g_Vh[BHq * Sq * DEPTHq];
__device__ float g_Z[NTOK * DMq];
__device__ float g_attn_fallback[(size_t)BHq * Sq * Sq];

// ---------------- tf32 helpers ----------------
__device__ __forceinline__ uint32_t f2tf32(float f) {
    uint32_t u;
    asm("cvt.rna.tf32.f32 %0, %1;" : "=r"(u) : "f"(f));
    return u;
}
__device__ __forceinline__ float tfbits(float f) {  // tf32 bits carried in a float
    return __uint_as_float(f2tf32(f));
}
__device__ __forceinline__ void mma8(float* c, const uint32_t* a, const uint32_t* b) {
    asm volatile(
        "mma.sync.aligned.m16n8k8.row.col.f32.tf32.tf32.f32 "
        "{%0,%1,%2,%3}, {%4,%5,%6,%7}, {%8,%9}, {%0,%1,%2,%3};"
        : "+f"(c[0]), "+f"(c[1]), "+f"(c[2]), "+f"(c[3])
        : "r"(a[0]), "r"(a[1]), "r"(a[2]), "r"(a[3]),
          "r"(b[0]), "r"(b[1]));
}

// Fragment smem layout: float2 arr[2 stage][2 kc][DIM][4 lt]
//   arr[st][kc][row][lt] = ( X[row][kc*8+lt] , X[row][kc*8+lt+4] )  (tf32 bits)
// A-frag (rows lg,lg+8): 2x LDS.64 ; B-frag (col lg): 1x LDS.64.

// Pack a row's 8 k-values (two float4: k0..3, k4..7) into frag layout, 2x STS.128.
__device__ __forceinline__ void sts_row8(float2* base /* &arr[st][kc][row][0] */,
                                         float4 v0, float4 v1) {
    float4 w0 = make_float4(tfbits(v0.x), tfbits(v1.x), tfbits(v0.y), tfbits(v1.y));
    float4 w1 = make_float4(tfbits(v0.z), tfbits(v1.z), tfbits(v0.w), tfbits(v1.w));
    *reinterpret_cast<float4*>(base)     = w0;  // lt 0,1
    *reinterpret_cast<float4*>(base + 2) = w1;  // lt 2,3
}

// ============================================================
// Kernel 1: proj  C[8192x1536] = [emb;pe] @ [Wq|Wk|Wv] + bias
// 128x128 tile, BK=16, double-buffered, 256 thr (8 warps 2x4).
// ============================================================
__global__ void __launch_bounds__(256)
proj_gemm_tc(const float* __restrict__ emb, const float* __restrict__ pe,
             const float* __restrict__ Wq, const float* __restrict__ bq,
             const float* __restrict__ Wk, const float* __restrict__ bk,
             const float* __restrict__ Wv, const float* __restrict__ bv) {
    __shared__ float2 As2[2][2][128][4];
    __shared__ float2 Bs2[2][2][128][4];

    const int m0 = blockIdx.y * 128;
    const int n0 = blockIdx.x * 128;
    const int tid = threadIdx.x;
    const int wid = tid >> 5, lane = tid & 31;
    const int wm = (wid >> 2) * 64, wn = (wid & 3) * 32;
    const int lg = lane >> 2, lt = lane & 3;

    // block-uniform source / weight / bias selection
    const float* srcA = (m0 < NTOK) ? (emb + (size_t)m0 * DMq)
                                    : (pe + (size_t)(m0 - NTOK) * DMq);
    const float* W    = (n0 < 512) ? Wq : (n0 < 1024 ? Wk : Wv);
    const float* bias = (n0 < 512) ? bq : (n0 < 1024 ? bk : bv);
    const int colbase = n0 & 511;

    // staging thread maps
    const int sm = tid >> 1;          // A row 0..127
    const int skc = tid & 1;          // A k-chunk
    const int bk_ = tid >> 4;         // B k-row 0..15
    const int bn_ = (tid & 15) * 8;   // B col 0..120

    float acc[4][4][4];
#pragma unroll
    for (int i = 0; i < 4; i++)
#pragma unroll
        for (int j = 0; j < 4; j++)
#pragma unroll
            for (int r = 0; r < 4; r++) acc[i][j][r] = 0.f;

    const int NIT = DMq / 16;  // 32

    // prologue: fill stage 0
    {
        const float* ap = srcA + (size_t)sm * DMq + skc * 8;
        float4 a0 = *(const float4*)(ap);
        float4 a1 = *(const float4*)(ap + 4);
        sts_row8(&As2[0][skc][sm][0], a0, a1);
        const float* bp = W + (size_t)bk_ * DMq + colbase + bn_;
        float4 b0 = *(const float4*)(bp);
        float4 b1 = *(const float4*)(bp + 4);
        int kc = bk_ >> 3, lts = bk_ & 3, half = (bk_ >> 2) & 1;
        float* d0 = (float*)&Bs2[0][kc][bn_][lts] + half;
        d0[0] = tfbits(b0.x); d0[8] = tfbits(b0.y); d0[16] = tfbits(b0.z); d0[24] = tfbits(b0.w);
        d0[32] = tfbits(b1.x); d0[40] = tfbits(b1.y); d0[48] = tfbits(b1.z); d0[56] = tfbits(b1.w);
    }
    __syncthreads();

    for (int it = 0; it < NIT; it++) {
        const int st = it & 1;
        float4 a0, a1, b0, b1;
        const bool more = (it + 1 < NIT);
        if (more) {
            int k0 = (it + 1) * 16;
            const float* ap = srcA + (size_t)sm * DMq + k0 + skc * 8;
            a0 = *(const float4*)(ap);
            a1 = *(const float4*)(ap + 4);
            const float* bp = W + (size_t)(k0 + bk_) * DMq + colbase + bn_;
            b0 = *(const float4*)(bp);
            b1 = *(const float4*)(bp + 4);
        }
        // compute current stage
#pragma unroll
        for (int kc = 0; kc < 2; kc++) {
            uint32_t af[4][4], bf[4][2];
#pragma unroll
            for (int mi = 0; mi < 4; mi++) {
                float2 x0 = As2[st][kc][wm + mi * 16 + lg][lt];
                float2 x1 = As2[st][kc][wm + mi * 16 + 8 + lg][lt];
                af[mi][0] = __float_as_uint(x0.x);
                af[mi][1] = __float_as_uint(x1.x);
                af[mi][2] = __float_as_uint(x0.y);
                af[mi][3] = __float_as_uint(x1.y);
            }
#pragma unroll
            for (int ni = 0; ni < 4; ni++) {
                float2 y = Bs2[st][kc][wn + ni * 8 + lg][lt];
                bf[ni][0] = __float_as_uint(y.x);
                bf[ni][1] = __float_as_uint(y.y);
            }
#pragma unroll
            for (int mi = 0; mi < 4; mi++)
#pragma unroll
                for (int ni = 0; ni < 4; ni++) mma8(acc[mi][ni], af[mi], bf[ni]);
        }
        if (more) {
            sts_row8(&As2[st ^ 1][skc][sm][0], a0, a1);
            int kc = bk_ >> 3, lts = bk_ & 3, half = (bk_ >> 2) & 1;
            float* d0 = (float*)&Bs2[st ^ 1][kc][bn_][lts] + half;
            d0[0] = tfbits(b0.x); d0[8] = tfbits(b0.y); d0[16] = tfbits(b0.z); d0[24] = tfbits(b0.w);
            d0[32] = tfbits(b1.x); d0[40] = tfbits(b1.y); d0[48] = tfbits(b1.z); d0[56] = tfbits(b1.w);
        }
        __syncthreads();
    }

#pragma unroll
    for (int mi = 0; mi < 4; mi++) {
        int r0 = m0 + wm + mi * 16 + lg;
#pragma unroll
        for (int ni = 0; ni < 4; ni++) {
            int c0 = n0 + wn + ni * 8 + 2 * lt;
            float bv0 = bias[(c0) & 511], bv1 = bias[(c0 + 1) & 511];
            *reinterpret_cast<float2*>(&g_C[(size_t)r0 * CC + c0]) =
                make_float2(acc[mi][ni][0] + bv0, acc[mi][ni][1] + bv1);
            *reinterpret_cast<float2*>(&g_C[(size_t)(r0 + 8) * CC + c0]) =
                make_float2(acc[mi][ni][2] + bv0, acc[mi][ni][3] + bv1);
        }
    }
}

// ============================================================
// Kernel 2: rearrange (unchanged)
// ============================================================
__global__ void rearrange_kernel() {
    int idx = blockIdx.x * blockDim.x + threadIdx.x;
    if (idx >= NTOK * DMq) return;
    int n = idx / DMq;
    int c = idx % DMq;
    int b = n / Sq, s = n % Sq;
    int h = c / DEPTHq, d = c % DEPTHq;

    float Qc = g_C[(size_t)n * CC + c];
    float Qr = g_C[(size_t)(NTOK + n) * CC + c];
    float Kc = g_C[(size_t)n * CC + 512 + c];
    float Kr = g_C[(size_t)(NTOK + n) * CC + 512 + c];
    float Vv = g_C[(size_t)n * CC + 1024 + c];

    size_t base = ((size_t)(b * Hq + h) * Sq + s) * 128;
    g_Qh[base + d]      = (Qc + Qr) * 0.125f;
    g_Qh[base + 64 + d] = Qc * 0.125f;
    g_Kh[base + d]      = Kc;
    g_Kh[base + 64 + d] = Kr;
    g_Vh[((size_t)(b * Hq + h) * Sq + s) * DEPTHq + d] = Vv;
}

// ============================================================
// Kernel 3: logits per (b,h): L = Q̂ @ K̂^T, K-dim 128.
// Both operands row-major [row][128] → identical staging paths.
// ============================================================
__global__ void __launch_bounds__(256)
logits_gemm_tc(float* __restrict__ attn) {
    __shared__ float2 As2[2][2][128][4];
    __shared__ float2 Bs2[2][2][128][4];

    const int bh = blockIdx.z;
    const int q0 = blockIdx.y * 128;
    const int t0 = blockIdx.x * 128;
    const float* Q = g_Qh + (size_t)bh * Sq * 128;
    const float* K = g_Kh + (size_t)bh * Sq * 128;
    float* out = attn + (size_t)bh * Sq * Sq;

    const int tid = threadIdx.x;
    const int wid = tid >> 5, lane = tid & 31;
    const int wm = (wid >> 2) * 64, wn = (wid & 3) * 32;
    const int lg = lane >> 2, lt = lane & 3;

    const int sm = tid >> 1;
    const int skc = tid & 1;

    float acc[4][4][4];
#pragma unroll
    for (int i = 0; i < 4; i++)
#pragma unroll
        for (int j = 0; j < 4; j++)
#pragma unroll
            for (int r = 0; r < 4; r++) acc[i][j][r] = 0.f;

    const int NIT = 128 / 16;  // 8

    {
        const float* ap = Q + (size_t)(q0 + sm) * 128 + skc * 8;
        sts_row8(&As2[0][skc][sm][0], *(const float4*)ap, *(const float4*)(ap + 4));
        const float* bp = K + (size_t)(t0 + sm) * 128 + skc * 8;
        sts_row8(&Bs2[0][skc][sm][0], *(const float4*)bp, *(const float4*)(bp + 4));
    }
    __syncthreads();

    for (int it = 0; it < NIT; it++) {
        const int st = it & 1;
        float4 a0, a1, b0, b1;
        const bool more = (it + 1 < NIT);
        if (more) {
            int k0 = (it + 1) * 16;
            const float* ap = Q + (size_t)(q0 + sm) * 128 + k0 + skc * 8;
            a0 = *(const float4*)(ap);
            a1 = *(const float4*)(ap + 4);
            const float* bp = K + (size_t)(t0 + sm) * 128 + k0 + skc * 8;
            b0 = *(const float4*)(bp);
            b1 = *(const float4*)(bp + 4);
        }
#pragma unroll
        for (int kc = 0; kc < 2; kc++) {
            uint32_t af[4][4], bf[4][2];
#pragma unroll
            for (int mi = 0; mi < 4; mi++) {
                float2 x0 = As2[st][kc][wm + mi * 16 + lg][lt];
                float2 x1 = As2[st][kc][wm + mi * 16 + 8 + lg][lt];
                af[mi][0] = __float_as_uint(x0.x);
                af[mi][1] = __float_as_uint(x1.x);
                af[mi][2] = __float_as_uint(x0.y);
                af[mi][3] = __float_as_uint(x1.y);
            }
#pragma unroll
            for (int ni = 0; ni < 4; ni++) {
                float2 y = Bs2[st][kc][wn + ni * 8 + lg][lt];
                bf[ni][0] = __float_as_uint(y.x);
                bf[ni][1] = __float_as_uint(y.y);
            }
#pragma unroll
            for (int mi = 0; mi < 4; mi++)
#pragma unroll
                for (int ni = 0; ni < 4; ni++) mma8(acc[mi][ni], af[mi], bf[ni]);
        }
        if (more) {
            sts_row8(&As2[st ^ 1][skc][sm][0], a0, a1);
            sts_row8(&Bs2[st ^ 1][skc][sm][0], b0, b1);
        }
        __syncthreads();
    }

#pragma unroll
    for (int mi = 0; mi < 4; mi++) {
        int r0 = q0 + wm + mi * 16 + lg;
#pragma unroll
        for (int ni = 0; ni < 4; ni++) {
            int c0 = t0 + wn + ni * 8 + 2 * lt;
            *reinterpret_cast<float2*>(&out[(size_t)r0 * Sq + c0]) =
                make_float2(acc[mi][ni][0], acc[mi][ni][1]);
            *reinterpret_cast<float2*>(&out[(size_t)(r0 + 8) * Sq + c0]) =
                make_float2(acc[mi][ni][2], acc[mi][ni][3]);
        }
    }
}

// ============================================================
// Kernel 4: softmax (unchanged; 81% DRAM SOL)
// ============================================================
__global__ void softmax_kernel(float* __restrict__ attn) {
    size_t row = blockIdx.x;
    float* p = attn + row * Sq;
    const int tid = threadIdx.x;

    float v[8];
    float m = -1e30f;
#pragma unroll
    for (int i = 0; i < 8; i++) {
        v[i] = p[tid + i * 256];
        m = fmaxf(m, v[i]);
    }
    __shared__ float redmax[8];
    __shared__ float redsum[8];
#pragma unroll
    for (int o = 16; o > 0; o >>= 1) m = fmaxf(m, __shfl_xor_sync(0xffffffffu, m, o));
    if ((tid & 31) == 0) redmax[tid >> 5] = m;
    __syncthreads();
    float mm = redmax[0];
#pragma unroll
    for (int i = 1; i < 8; i++) mm = fmaxf(mm, redmax[i]);

    float ssum = 0.f;
#pragma unroll
    for (int i = 0; i < 8; i++) {
        v[i] = __expf(v[i] - mm);
        ssum += v[i];
    }
#pragma unroll
    for (int o = 16; o > 0; o >>= 1) ssum += __shfl_xor_sync(0xffffffffu, ssum, o);
    if ((tid & 31) == 0) redsum[tid >> 5] = ssum;
    __syncthreads();
    float tot = 0.f;
#pragma unroll
    for (int i = 0; i < 8; i++) tot += redsum[i];
    float inv = 1.f / tot;
#pragma unroll
    for (int i = 0; i < 8; i++) p[tid + i * 256] = v[i] * inv;
}

// ============================================================
// Kernel 5: z = attn @ V per (b,h): [2048x2048]@[2048x64]
// 128x64 tile, BK=16 double-buffered, 256 thr (8 warps 4x2),
// warp tile 32x32.
// ============================================================
__global__ void __launch_bounds__(256)
zv_gemm_tc(const float* __restrict__ attn) {
    __shared__ float2 As2[2][2][128][4];
    __shared__ float2 Bs2[2][2][64][4];

    const int bh = blockIdx.y;
    const int q0 = blockIdx.x * 128;
    const int b = bh / Hq, h = bh % Hq;
    const float* P = attn + (size_t)bh * Sq * Sq;
    const float* V = g_Vh + (size_t)bh * Sq * DEPTHq;

    const int tid = threadIdx.x;
    const int wid = tid >> 5, lane = tid & 31;
    const int wm = (wid >> 1) * 32, wn = (wid & 1) * 32;
    const int lg = lane >> 2, lt = lane & 3;

    const int sm = tid >> 1;
    const int skc = tid & 1;
    const int bk_ = tid >> 4;        // V k-row 0..15
    const int bn_ = (tid & 15) * 4;  // V col 0..60

    float acc[2][4][4];
#pragma unroll
    for (int i = 0; i < 2; i++)
#pragma unroll
        for (int j = 0; j < 4; j++)
#pragma unroll
            for (int r = 0; r < 4; r++) acc[i][j][r] = 0.f;

    const int NIT = Sq / 16;  // 128

    {
        const float* ap = P + (size_t)(q0 + sm) * Sq + skc * 8;
        sts_row8(&As2[0][skc][sm][0], *(const float4*)ap, *(const float4*)(ap + 4));
        float4 bv = *(const float4*)(V + (size_t)bk_ * DEPTHq + bn_);
        int kc = bk_ >> 3, lts = bk_ & 3, half = (bk_ >> 2) & 1;
        float* d0 = (float*)&Bs2[0][kc][bn_][lts] + half;
        d0[0] = tfbits(bv.x); d0[8] = tfbits(bv.y); d0[16] = tfbits(bv.z); d0[24] = tfbits(bv.w);
    }
    __syncthreads();

    for (int it = 0; it < NIT; it++) {
        const int st = it & 1;
        float4 a0, a1, bv;
        const bool more = (it + 1 < NIT);
        if (more) {
            int k0 = (it + 1) * 16;
            const float* ap = P + (size_t)(q0 + sm) * Sq + k0 + skc * 8;
            a0 = *(const float4*)(ap);
            a1 = *(const float4*)(ap + 4);
            bv = *(const float4*)(V + (size_t)(k0 + bk_) * DEPTHq + bn_);
        }
#pragma unroll
        for (int kc = 0; kc < 2; kc++) {
            uint32_t af[2][4], bf[4][2];
#pragma unroll
            for (int mi = 0; mi < 2; mi++) {
                float2 x0 = As2[st][kc][wm + mi * 16 + lg][lt];
                float2 x1 = As2[st][kc][wm + mi * 16 + 8 + lg][lt];
                af[mi][0] = __float_as_uint(x0.x);
                af[mi][1] = __float_as_uint(x1.x);
                af[mi][2] = __float_as_uint(x0.y);
                af[mi][3] = __float_as_uint(x1.y);
            }
#pragma unroll
            for (int ni = 0; ni < 4; ni++) {
                float2 y = Bs2[st][kc][wn + ni * 8 + lg][lt];
                bf[ni][0] = __float_as_uint(y.x);
                bf[ni][1] = __float_as_uint(y.y);
            }
#pragma unroll
            for (int mi = 0; mi < 2; mi++)
#pragma unroll
                for (int ni = 0; ni < 4; ni++) mma8(acc[mi][ni], af[mi], bf[ni]);
        }
        if (more) {
            sts_row8(&As2[st ^ 1][skc][sm][0], a0, a1);
            int kc = bk_ >> 3, lts = bk_ & 3, half = (bk_ >> 2) & 1;
            float* d0 = (float*)&Bs2[st ^ 1][kc][bn_][lts] + half;
            d0[0] = tfbits(bv.x); d0[8] = tfbits(bv.y); d0[16] = tfbits(bv.z); d0[24] = tfbits(bv.w);
        }
        __syncthreads();
    }

#pragma unroll
    for (int mi = 0; mi < 2; mi++) {
        int r0 = q0 + wm + mi * 16 + lg;
#pragma unroll
        for (int ni = 0; ni < 4; ni++) {
            int c0 = wn + ni * 8 + 2 * lt;
            size_t base0 = ((size_t)b * Sq + r0) * DMq + h * DEPTHq + c0;
            size_t base1 = ((size_t)b * Sq + r0 + 8) * DMq + h * DEPTHq + c0;
            *reinterpret_cast<float2*>(&g_Z[base0]) =
                make_float2(acc[mi][ni][0], acc[mi][ni][1]);
            *reinterpret_cast<float2*>(&g_Z[base1]) =
                make_float2(acc[mi][ni][2], acc[mi][ni][3]);
        }
    }
}

// ============================================================
// Kernel 6: out = z @ Wo + bo : [4096x512]@[512x512]
// ============================================================
__global__ void __launch_bounds__(256)
out_gemm_tc(const float* __restrict__ Wo, const float* __restrict__ bo,
            float* __restrict__ out) {
    __shared__ float2 As2[2][2][128][4];
    __shared__ float2 Bs2[2][2][128][4];

    const int m0 = blockIdx.y * 128;
    const int n0 = blockIdx.x * 128;
    const int tid = threadIdx.x;
    const int wid = tid >> 5, lane = tid & 31;
    const int wm = (wid >> 2) * 64, wn = (wid & 3) * 32;
    const int lg = lane >> 2, lt = lane & 3;

    const int sm = tid >> 1;
    const int skc = tid & 1;
    const int bk_ = tid >> 4;
    const int bn_ = (tid & 15) * 8;

    float acc[4][4][4];
#pragma unroll
    for (int i = 0; i < 4; i++)
#pragma unroll
        for (int j = 0; j < 4; j++)
#pragma unroll
            for (int r = 0; r < 4; r++) acc[i][j][r] = 0.f;

    const int NIT = DMq / 16;  // 32

    {
        const float* ap = g_Z + (size_t)(m0 + sm) * DMq + skc * 8;
        sts_row8(&As2[0][skc][sm][0], *(const float4*)ap, *(const float4*)(ap + 4));
        const float* bp = Wo + (size_t)bk_ * DMq + n0 + bn_;
        float4 b0 = *(const float4*)(bp);
        float4 b1 = *(const float4*)(bp + 4);
        int kc = bk_ >> 3, lts = bk_ & 3, half = (bk_ >> 2) & 1;
        float* d0 = (float*)&Bs2[0][kc][bn_][lts] + half;
        d0[0] = tfbits(b0.x); d0[8] = tfbits(b0.y); d0[16] = tfbits(b0.z); d0[24] = tfbits(b0.w);
        d0[32] = tfbits(b1.x); d0[40] = tfbits(b1.y); d0[48] = tfbits(b1.z); d0[56] = tfbits(b1.w);
    }
    __syncthreads();

    for (int it = 0; it < NIT; it++) {
        const int st = it & 1;
        float4 a0, a1, b0, b1;
        const bool more = (it + 1 < NIT);
        if (more) {
            int k0 = (it + 1) * 16;
            const float* ap = g_Z + (size_t)(m0 + sm) * DMq + k0 + skc * 8;
            a0 = *(const float4*)(ap);
            a1 = *(const float4*)(ap + 4);
            const float* bp = Wo + (size_t)(k0 + bk_) * DMq + n0 + bn_;
            b0 = *(const float4*)(bp);
            b1 = *(const float4*)(bp + 4);
        }
#pragma unroll
        for (int kc = 0; kc < 2; kc++) {
            uint32_t af[4][4], bf[4][2];
#pragma unroll
            for (int mi = 0; mi < 4; mi++) {
                float2 x0 = As2[st][kc][wm + mi * 16 + lg][lt];
                float2 x1 = As2[st][kc][wm + mi * 16 + 8 + lg][lt];
                af[mi][0] = __float_as_uint(x0.x);
                af[mi][1] = __float_as_uint(x1.x);
                af[mi][2] = __float_as_uint(x0.y);
                af[mi][3] = __float_as_uint(x1.y);
            }
#pragma unroll
            for (int ni = 0; ni < 4; ni++) {
                float2 y = Bs2[st][kc][wn + ni * 8 + lg][lt];
                bf[ni][0] = __float_as_uint(y.x);
                bf[ni][1] = __float_as_uint(y.y);
            }
#pragma unroll
            for (int mi = 0; mi < 4; mi++)
#pragma unroll
                for (int ni = 0; ni < 4; ni++) mma8(acc[mi][ni], af[mi], bf[ni]);
        }
        if (more) {
            sts_row8(&As2[st ^ 1][skc][sm][0], a0, a1);
            int kc = bk_ >> 3, lts = bk_ & 3, half = (bk_ >> 2) & 1;
            float* d0 = (float*)&Bs2[st ^ 1][kc][bn_][lts] + half;
            d0[0] = tfbits(b0.x); d0[8] = tfbits(b0.y); d0[16] = tfbits(b0.z); d0[24] = tfbits(b0.w);
            d0[32] = tfbits(b1.x); d0[40] = tfbits(b1.y); d0[48] = tfbits(b1.z); d0[56] = tfbits(b1.w);
        }
        __syncthreads();
    }

#pragma unroll
    for (int mi = 0; mi < 4; mi++) {
        int r0 = m0 + wm + mi * 16 + lg;
#pragma unroll
        for (int ni = 0; ni < 4; ni++) {
            int c0 = n0 + wn + ni * 8 + 2 * lt;
            float bv0 = bo[c0], bv1 = bo[c0 + 1];
            *reinterpret_cast<float2*>(&out[(size_t)r0 * DMq + c0]) =
                make_float2(acc[mi][ni][0] + bv0, acc[mi][ni][1] + bv1);
            *reinterpret_cast<float2*>(&out[(size_t)(r0 + 8) * DMq + c0]) =
                make_float2(acc[mi][ni][2] + bv0, acc[mi][ni][3] + bv1);
        }
    }
}

// ============================================================
// Launch
// ============================================================
extern "C" void kernel_launch(void* const* d_in, const int* in_sizes, int n_in,
                              void* d_out, int out_size) {
    const float* emb = (const float*)d_in[0];
    const float* pe  = (const float*)d_in[1];
    const float* Wq  = (const float*)d_in[2];
    const float* bq  = (const float*)d_in[3];
    const float* Wk  = (const float*)d_in[4];
    const float* bk  = (const float*)d_in[5];
    const float* Wv  = (const float*)d_in[6];
    const float* bv  = (const float*)d_in[7];
    const float* Wo  = (const float*)d_in[8];
    const float* bo  = (const float*)d_in[9];

    float* out = (float*)d_out;

    const long long need = (long long)NTOK * DMq + (long long)BHq * Sq * Sq;
    float* attn;
    if ((long long)out_size >= need) {
        attn = out + (size_t)NTOK * DMq;
    } else {
        float* p = nullptr;
        cudaGetSymbolAddress((void**)&p, g_attn_fallback);
        attn = p;
    }

    {
        dim3 grid(CC / 128, NROWS / 128);
        proj_gemm_tc<<<grid, 256>>>(emb, pe, Wq, bq, Wk, bk, Wv, bv);
    }
    {
        int total = NTOK * DMq;
        rearrange_kernel<<<(total + 255) / 256, 256>>>();
    }
    {
        dim3 grid(Sq / 128, Sq / 128, BHq);
        logits_gemm_tc<<<grid, 256>>>(attn);
    }
    {
        softmax_kernel<<<BHq * Sq, 256>>>(attn);
    }
    {
        dim3 grid(Sq / 128, BHq);
        zv_gemm_tc<<<grid, 256>>>(attn);
    }
    {
        dim3 grid(DMq / 128, NTOK / 128);
        out_gemm_tc<<<grid, 256>>>(Wo, bo, out);
    }
}